// round 1
// baseline (speedup 1.0000x reference)
#include <cuda_runtime.h>
#include <math_constants.h>

static constexpr int NPTS = 4096;   // N source points
static constexpr int NUP  = 16384;  // upsampled points per batch
static constexpr int BATCH = 4;
static constexpr int C    = 64;     // channels == DIM
static constexpr int TPB  = 256;    // threads per block == queries per block

static constexpr int SMEM_BYTES = NPTS * 16 + C * C * 4 + C * 4; // pos(float4) + W + b = 82176

__global__ void __launch_bounds__(TPB, 2)
up_kernel(const float* __restrict__ feature,
          const float* __restrict__ pos,
          const float* __restrict__ pos_up,
          const float* __restrict__ W,
          const float* __restrict__ bias,
          float* __restrict__ out)
{
    extern __shared__ float sm[];
    float4* spos = reinterpret_cast<float4*>(sm);   // [NPTS] : x,y,z, 0.5*|p|^2
    float*  sW   = sm + NPTS * 4;                   // [C*C]  : W row-major (c, d)
    float*  sb   = sW + C * C;                      // [C]

    const int b   = blockIdx.y;
    const int tid = threadIdx.x;

    // ---- stage pos (with half-norm), W, bias into smem ----
    {
        const float* pb = pos + (size_t)b * NPTS * 3;
        for (int j = tid; j < NPTS; j += TPB) {
            float x = pb[3 * j + 0];
            float y = pb[3 * j + 1];
            float z = pb[3 * j + 2];
            spos[j] = make_float4(x, y, z, 0.5f * (x * x + y * y + z * z));
        }
        for (int i = tid; i < C * C; i += TPB) sW[i] = W[i];
        if (tid < C) sb[tid] = bias[tid];
    }
    __syncthreads();

    // ---- per-query setup ----
    const int q = blockIdx.x * TPB + tid;
    const float* pu = pos_up + (size_t)(b * NUP + q) * 3;
    const float pux = pu[0], puy = pu[1], puz = pu[2];
    const float nu  = pux * pux + puy * puy + puz * puz;

    // ---- distance scan + top-3 (ascending: v0 <= v1 <= v2), strict '<' keeps
    //      the earliest index on ties, matching jax.lax.top_k stability ----
    float v0 = CUDART_INF_F, v1 = CUDART_INF_F, v2 = CUDART_INF_F;
    int   i0 = 0, i1 = 0, i2 = 0;

    #pragma unroll 8
    for (int j = 0; j < NPTS; ++j) {
        float4 p = spos[j];
        // s = 0.5|p|^2 - pu.p  (monotone in d^2 = 2s + |pu|^2)
        float s = __fmaf_rn(-pux, p.x, p.w);
        s = __fmaf_rn(-puy, p.y, s);
        s = __fmaf_rn(-puz, p.z, s);
        if (s < v2) {
            if (s < v1) {
                v2 = v1; i2 = i1;
                if (s < v0) { v1 = v0; i1 = i0; v0 = s; i0 = j; }
                else        { v1 = s;  i1 = j; }
            } else { v2 = s; i2 = j; }
        }
    }

    // ---- inverse-distance weights, normalized ----
    float w0 = 1.0f / (__fmaf_rn(2.0f, v0, nu) + 1e-6f);
    float w1 = 1.0f / (__fmaf_rn(2.0f, v1, nu) + 1e-6f);
    float w2 = 1.0f / (__fmaf_rn(2.0f, v2, nu) + 1e-6f);
    float inv = 1.0f / (w0 + w1 + w2);
    w0 *= inv; w1 *= inv; w2 *= inv;

    const float4* f0 = reinterpret_cast<const float4*>(feature + (size_t)(b * NPTS + i0) * C);
    const float4* f1 = reinterpret_cast<const float4*>(feature + (size_t)(b * NPTS + i1) * C);
    const float4* f2 = reinterpret_cast<const float4*>(feature + (size_t)(b * NPTS + i2) * C);

    // ---- fused interp + 64x64 GEMM + bias, 64 register accumulators ----
    float acc[64];
    #pragma unroll
    for (int d = 0; d < 64; ++d) acc[d] = sb[d];

    // rolled over c4 (16 iters) to keep code in L0 I$; inner loops fully
    // unrolled so acc[] indices are compile-time constants (registers).
    for (int c4 = 0; c4 < 16; ++c4) {
        float4 a = __ldg(f0 + c4);
        float4 e = __ldg(f1 + c4);
        float4 g = __ldg(f2 + c4);
        float nf[4];
        nf[0] = __fmaf_rn(w0, a.x, __fmaf_rn(w1, e.x, w2 * g.x));
        nf[1] = __fmaf_rn(w0, a.y, __fmaf_rn(w1, e.y, w2 * g.y));
        nf[2] = __fmaf_rn(w0, a.z, __fmaf_rn(w1, e.z, w2 * g.z));
        nf[3] = __fmaf_rn(w0, a.w, __fmaf_rn(w1, e.w, w2 * g.w));

        const float4* wr = reinterpret_cast<const float4*>(sW + (size_t)c4 * 4 * C);
        #pragma unroll
        for (int k = 0; k < 4; ++k) {          // the 4 channels in this c4
            float nfc = nf[k];
            #pragma unroll
            for (int m = 0; m < 16; ++m) {     // 64 outputs as 16 float4 W loads
                float4 wv = wr[k * 16 + m];
                acc[4 * m + 0] = __fmaf_rn(nfc, wv.x, acc[4 * m + 0]);
                acc[4 * m + 1] = __fmaf_rn(nfc, wv.y, acc[4 * m + 1]);
                acc[4 * m + 2] = __fmaf_rn(nfc, wv.z, acc[4 * m + 2]);
                acc[4 * m + 3] = __fmaf_rn(nfc, wv.w, acc[4 * m + 3]);
            }
        }
    }

    // ---- ReLU + vectorized store ----
    float4* o4 = reinterpret_cast<float4*>(out + (size_t)(b * NUP + q) * C);
    #pragma unroll
    for (int m = 0; m < 16; ++m) {
        float4 v;
        v.x = fmaxf(acc[4 * m + 0], 0.0f);
        v.y = fmaxf(acc[4 * m + 1], 0.0f);
        v.z = fmaxf(acc[4 * m + 2], 0.0f);
        v.w = fmaxf(acc[4 * m + 3], 0.0f);
        o4[m] = v;
    }
}

extern "C" void kernel_launch(void* const* d_in, const int* in_sizes, int n_in,
                              void* d_out, int out_size)
{
    const float* feature = (const float*)d_in[0];
    const float* pos     = (const float*)d_in[1];
    const float* pos_up  = (const float*)d_in[2];
    const float* W       = (const float*)d_in[3];
    const float* bias    = (const float*)d_in[4];
    float* out = (float*)d_out;

    cudaFuncSetAttribute(up_kernel, cudaFuncAttributeMaxDynamicSharedMemorySize, SMEM_BYTES);

    dim3 grid(NUP / TPB, BATCH);
    up_kernel<<<grid, TPB, SMEM_BYTES>>>(feature, pos, pos_up, W, bias, out);
}